// round 8
// baseline (speedup 1.0000x reference)
#include <cuda_runtime.h>
#include <math.h>

#define NP 256        // particles
#define ND 3
#define NR 64         // rbfs
#define NH 128        // hidden
#define NB 16         // batch
#define FEPS 1e-6f

#define K_TAB 256
#define D_MAX 12.0f
#define E_PER_BLK 2   // table entries per build block

__device__ float g_tab[K_TAB];   // stores -2 * g(d)

__device__ __forceinline__ unsigned long long pack2(float lo, float hi) {
    unsigned long long p;
    asm("mov.b64 %0, {%1, %2};" : "=l"(p) : "f"(lo), "f"(hi));
    return p;
}

__device__ __forceinline__ float fast_tanh(float a) {
    float e = __expf(2.0f * a);
    return 1.0f - __fdividef(2.0f, e + 1.0f);
}

// ---------------------------------------------------------------------------
// Kernel 1: tabulate -2*g(d), g(d) = d/dd [ W2 . tanh(rbf(d) @ W1 + b1) ]
// Grid 128 (one wave), 128 threads = 1 hidden unit each, 2 entries/block.
// Fast MUFU-based exp/tanh; packed f32x2 dual accumulation, 4 chains.
// ---------------------------------------------------------------------------
__global__ __launch_bounds__(128) void build_tab_kernel(
    const float* __restrict__ mus, const float* __restrict__ log_gammas,
    const float* __restrict__ W1, const float* __restrict__ b1,
    const float* __restrict__ W2)
{
    __shared__ unsigned long long rbf_pk[E_PER_BLK][NR];  // 1 KB
    __shared__ float partial[E_PER_BLK][4];

    const int tid = threadIdx.x;
    const int e0  = blockIdx.x * E_PER_BLK;
    const float step = D_MAX / (float)(K_TAB - 1);

    // Phase 1: E_PER_BLK*NR = 128 (entry,r) pairs, one per thread
    {
        int e = tid >> 6, r = tid & 63;
        float d   = (float)(e0 + e) * step;
        float gma = __expf(log_gammas[r]);
        float dm  = d - mus[r];
        float ex  = __expf(-gma * dm * dm);
        rbf_pk[e][r] = pack2(ex, -2.0f * gma * dm * ex);
    }

    // This thread's W1 column (h = tid), coalesced
    float w[NR];
#pragma unroll
    for (int r = 0; r < NR; r++) w[r] = W1[r * NH + tid];
    const float b1h = b1[tid];
    const float W2h = W2[tid];
    __syncthreads();

    const int warp = tid >> 5;
#pragma unroll
    for (int e = 0; e < E_PER_BLK; e++) {
        unsigned long long acc0 = pack2(b1h, 0.0f);   // {a, sb}
        unsigned long long acc1 = pack2(0.0f, 0.0f);
        unsigned long long acc2 = pack2(0.0f, 0.0f);
        unsigned long long acc3 = pack2(0.0f, 0.0f);
        const unsigned long long* rb = rbf_pk[e];
#pragma unroll
        for (int r = 0; r < NR; r += 4) {
            unsigned long long w0, w1, w2, w3;
            asm("mov.b64 %0, {%1, %1};" : "=l"(w0) : "f"(w[r + 0]));
            asm("mov.b64 %0, {%1, %1};" : "=l"(w1) : "f"(w[r + 1]));
            asm("mov.b64 %0, {%1, %1};" : "=l"(w2) : "f"(w[r + 2]));
            asm("mov.b64 %0, {%1, %1};" : "=l"(w3) : "f"(w[r + 3]));
            asm("fma.rn.f32x2 %0, %1, %2, %0;" : "+l"(acc0) : "l"(rb[r + 0]), "l"(w0));
            asm("fma.rn.f32x2 %0, %1, %2, %0;" : "+l"(acc1) : "l"(rb[r + 1]), "l"(w1));
            asm("fma.rn.f32x2 %0, %1, %2, %0;" : "+l"(acc2) : "l"(rb[r + 2]), "l"(w2));
            asm("fma.rn.f32x2 %0, %1, %2, %0;" : "+l"(acc3) : "l"(rb[r + 3]), "l"(w3));
        }
        float a0, s0, a1, s1, a2, s2, a3, s3;
        asm("mov.b64 {%0, %1}, %2;" : "=f"(a0), "=f"(s0) : "l"(acc0));
        asm("mov.b64 {%0, %1}, %2;" : "=f"(a1), "=f"(s1) : "l"(acc1));
        asm("mov.b64 {%0, %1}, %2;" : "=f"(a2), "=f"(s2) : "l"(acc2));
        asm("mov.b64 {%0, %1}, %2;" : "=f"(a3), "=f"(s3) : "l"(acc3));
        float a  = (a0 + a1) + (a2 + a3);
        float sb = (s0 + s1) + (s2 + s3);
        float t  = fast_tanh(a);
        float contrib = W2h * (1.0f - t * t) * sb;
#pragma unroll
        for (int off = 16; off > 0; off >>= 1)
            contrib += __shfl_xor_sync(0xFFFFFFFFu, contrib, off);
        if ((tid & 31) == 0) partial[e][warp] = contrib;
    }
    __syncthreads();
    if (tid < E_PER_BLK)
        g_tab[e0 + tid] = -2.0f * (partial[tid][0] + partial[tid][1]
                                 + partial[tid][2] + partial[tid][3]);
}

// ---------------------------------------------------------------------------
// Kernel 2: forces. Grid (NP/8, NB) = 512 blocks x 256 threads (6.9
// warps/scheduler): 8 i's per block, 32 threads per i (8 j each), fully
// unrolled, 5-level shfl combine.
// u-form quadratic interpolation: g = c0' + c1'*u + c2'*u^2 with node-k
// coefficients, so no I2F / t-subtraction / int clamps in the inner loop:
// per pair = 3 LDS + sub/FMA chain + RSQ + fminf + F2I + LDS.128 + 3 FMA.
// CoM mean subtraction skipped (pair antisymmetry: mean is rounding noise).
// ---------------------------------------------------------------------------
__global__ __launch_bounds__(256) void force_kernel(
    const float* __restrict__ xs, float* __restrict__ out)
{
    __shared__ float px[NP], py[NP], pz[NP];
    __shared__ float4 coef[K_TAB];

    const int b   = blockIdx.y;
    const int tid = threadIdx.x;

    const float* xb = xs + (size_t)b * NP * ND;
    // 768 floats over 256 threads
#pragma unroll
    for (int it = 0; it < 3; it++) {
        int idx = it * 256 + tid;
        float v = __ldg(xb + idx);
        int j = idx / 3, c = idx - j * 3;
        if (c == 0) px[j] = v; else if (c == 1) py[j] = v; else pz[j] = v;
    }
    // u-form quadratic coeffs: one node per thread
    {
        int k  = tid;
        int km = max(k - 1, 0), kp = min(k + 1, K_TAB - 1);
        float gm = g_tab[km], g0 = g_tab[k], gp = g_tab[kp];
        float c1 = 0.5f * (gp - gm);
        float c2 = 0.5f * (gp - 2.0f * g0 + gm);
        float fk = (float)k;
        // g(u) = g0 + c1*(u-k) + c2*(u-k)^2 expanded in u
        float c1u = c1 - 2.0f * c2 * fk;
        float c0u = g0 - c1 * fk + c2 * fk * fk;
        coef[k] = make_float4(c0u, c1u, c2, 0.0f);
    }
    __syncthreads();

    const int i = blockIdx.x * 8 + (tid >> 5);
    const int q = tid & 31;
    const float xi = px[i], yi = py[i], zi = pz[i];
    const float inv_step = (float)(K_TAB - 1) / D_MAX;

    float ax = 0.f, ay = 0.f, az = 0.f;
#pragma unroll
    for (int jj = 0; jj < NP / 32; jj++) {
        int j = jj * 32 + q;
        float rx = xi - px[j], ry = yi - py[j], rz = zi - pz[j];
        float d2 = fmaf(rx, rx, fmaf(ry, ry, fmaf(rz, rz, FEPS)));
        float inv_d = rsqrtf(d2);
        float u  = fminf(d2 * inv_d * inv_step, (float)(K_TAB - 2));
        int   k  = __float2int_rd(u);
        float4 c = coef[k];
        float g  = fmaf(u, fmaf(u, c.z, c.y), c.x);
        float s  = g * inv_d;          // j==i: r=0 -> contributes 0
        ax = fmaf(s, rx, ax);
        ay = fmaf(s, ry, ay);
        az = fmaf(s, rz, az);
    }
    // combine the 32 j-partitions (the warp shares i)
#pragma unroll
    for (int off = 1; off < 32; off <<= 1) {
        ax += __shfl_xor_sync(0xFFFFFFFFu, ax, off);
        ay += __shfl_xor_sync(0xFFFFFFFFu, ay, off);
        az += __shfl_xor_sync(0xFFFFFFFFu, az, off);
    }

    if (q == 0) {
        float* o = out + ((size_t)b * NP + i) * 3;
        o[0] = ax;    // -2 factor baked into g_tab
        o[1] = ay;
        o[2] = az;
    }
}

// ---------------------------------------------------------------------------
// Inputs (metadata order): t(1), xs(12288), mus(64), log_gammas(64),
//                          W1(8192), b1(128), W2(128), b2(1)
// Output: float32 (16, 256, 3)
// ---------------------------------------------------------------------------
extern "C" void kernel_launch(void* const* d_in, const int* in_sizes, int n_in,
                              void* d_out, int out_size)
{
    const float* xs  = (const float*)d_in[1];
    const float* mus = (const float*)d_in[2];
    const float* lg  = (const float*)d_in[3];
    const float* W1  = (const float*)d_in[4];
    const float* b1  = (const float*)d_in[5];
    const float* W2  = (const float*)d_in[6];
    float* out = (float*)d_out;

    build_tab_kernel<<<K_TAB / E_PER_BLK, 128>>>(mus, lg, W1, b1, W2);
    force_kernel<<<dim3(NP / 8, NB), 256>>>(xs, out);
}